// round 9
// baseline (speedup 1.0000x reference)
#include <cuda_runtime.h>
#include <cstdint>
#include <cstddef>

#define B   32
#define F   32
#define NP  1024
#define OC  32
#define K   8
#define TPB 256
#define PPC 256          // points per CTA
#define HP  128          // points per h-half thread group
#define PG  (NP / PPC)   // 4 point-groups per batch
#define MW  33           // padded words per bitmask row (conflict-free)

typedef unsigned long long ull;

// ---- f32x2 packed helpers (sm_103a full-rate fp32 path) ----
__device__ __forceinline__ ull pack2(float lo, float hi) {
    ull r; asm("mov.b64 %0, {%1, %2};" : "=l"(r) : "f"(lo), "f"(hi)); return r;
}
__device__ __forceinline__ void unpack2(ull v, float& lo, float& hi) {
    asm("mov.b64 {%0, %1}, %2;" : "=f"(lo), "=f"(hi) : "l"(v));
}
#define FMA2_ACC(d, a, b) asm("fma.rn.f32x2 %0, %1, %2, %0;" : "+l"(d) : "l"(a), "l"(b))

// smem: shx[F][NP] | rsh[NP] | wsum | wdif | cvec | mbits[PPC][MW]
//       | phv[2][PPC][K] | phi[2][PPC][K]
#define SMEM_FLOATS (F * NP + NP + OC * F + OC * F + OC + PPC * MW \
                     + 2 * PPC * K + 2 * PPC * K)

extern "C" __global__ void __launch_bounds__(TPB, 1)
nla_kernel(const float* __restrict__ x, const float* __restrict__ mask,
           const float* __restrict__ Wd, const float* __restrict__ bd,
           const float* __restrict__ Ws, const float* __restrict__ bs,
           const float* __restrict__ bias, float* __restrict__ out)
{
    extern __shared__ float smem[];
    float*    shx   = smem;                    // [F][NP]
    float*    rsh   = smem + F * NP;           // [NP]
    float*    wsum  = rsh + NP;                // [OC*F]  (Wd + Ws)
    float*    wdif  = wsum + OC * F;           // [OC*F]
    float*    cvec  = wdif + OC * F;           // [OC]
    unsigned* mbits = (unsigned*)(cvec + OC);  // [PPC][MW]
    float*    phv   = (float*)(mbits + PPC * MW);  // [2][PPC][K] partial vals
    int*      phi   = (int*)(phv + 2 * PPC * K);   // [2][PPC][K] partial idx

    const int tid   = threadIdx.x;
    const int p     = tid & (HP - 1);
    const int h     = tid >> 7;               // j-half
    const int batch = blockIdx.x / PG;
    const int grp   = blockIdx.x % PG;
    const int i1    = grp * PPC + p;          // first point
    const int i2    = i1 + HP;                // second point
    (void)mask;

    // ---- stage x[batch] (feature-major, contiguous) via float4 ----
    {
        const float4* xg = (const float4*)(x + (size_t)batch * F * NP);
        float4* xs = (float4*)shx;
        #pragma unroll
        for (int t = 0; t < (F * NP / 4) / TPB; ++t)
            xs[tid + t * TPB] = xg[tid + t * TPB];
    }
    for (int t = tid; t < OC * F; t += TPB) {
        float wd = Wd[t];
        wdif[t] = wd;
        wsum[t] = wd + Ws[t];
    }
    if (tid < OC) cvec[tid] = bd[tid] + bs[tid] + bias[tid];

    // ---- per-point mask bitmap from index math (== make_local_mask(32,32)) ----
    {
        unsigned* row = mbits + tid * MW;      // thread tid builds point tid's row
        #pragma unroll
        for (int w = 0; w < NP / 32; ++w) row[w] = 0u;

        int idx[8]; int n;
        const int ii = grp * PPC + tid;
        if (ii == 0)              { idx[0]=1;    idx[1]=32;   idx[2]=33;   n=3; }
        else if (ii == NP - 1)    { idx[0]=1022; idx[1]=991;  idx[2]=990;  n=3; }
        else if (ii == 31)        { idx[0]=30;   idx[1]=63;   idx[2]=62;   n=3; }
        else if (ii == NP - 32)   { idx[0]=993;  idx[1]=960;  idx[2]=961;  n=3; }
        else if (ii < 31)         { idx[0]=ii+1; idx[1]=ii-1; idx[2]=ii+31;
                                    idx[3]=ii+32; idx[4]=ii+33; n=5; }
        else if (ii > NP - 32)    { idx[0]=ii+1; idx[1]=ii-1; idx[2]=ii-33;
                                    idx[3]=ii-32; idx[4]=ii-31; n=5; }
        else if ((ii & 31) == 0)  { idx[0]=ii+1; idx[1]=ii-32; idx[2]=ii+32;
                                    idx[3]=ii-31; idx[4]=ii+33; n=5; }
        else if ((ii & 31) == 31) { idx[0]=ii-1; idx[1]=ii-32; idx[2]=ii+32;
                                    idx[3]=ii-33; idx[4]=ii+31; n=5; }
        else                      { idx[0]=ii+1; idx[1]=ii-1; idx[2]=ii-32;
                                    idx[3]=ii-31; idx[4]=ii-33; idx[5]=ii+32;
                                    idx[6]=ii+33; idx[7]=ii+31; n=8; }
        for (int t = 0; t < n; ++t)
            row[idx[t] >> 5] |= 1u << (idx[t] & 31);
    }
    __syncthreads();

    // ---- r[j] = sum_c x[c][j]^2 ----
    #pragma unroll
    for (int t = 0; t < NP / TPB; ++t) {
        int j = tid + t * TPB;
        float s = 0.f;
        #pragma unroll
        for (int c = 0; c < F; ++c) { float v = shx[c * NP + j]; s = fmaf(v, v, s); }
        rsh[j] = s;
    }
    __syncthreads();

    // ---- per-thread point features (scalar; packed on the fly) ----
    float xa[F], xb[F];
    #pragma unroll
    for (int c = 0; c < F; ++c) { xa[c] = shx[c * NP + i1]; xb[c] = shx[c * NP + i2]; }
    const float ri1 = rsh[i1], ri2 = rsh[i2];

    float tva[K], tvb[K]; int tia[K], tib[K];
    #pragma unroll
    for (int t = 0; t < K; ++t) {
        tva[t] = -3.4e38f; tia[t] = 0;
        tvb[t] = -3.4e38f; tib[t] = 0;
    }

    const unsigned* mra = mbits + p * MW;
    const unsigned* mrb = mbits + (p + HP) * MW;

    // h=0 arc starts just before both points' mask windows; each window is
    // visited contiguously in ascending index order (tie-critical interior
    // windows never wrap). h=1 arc is mask-free.
    const int warpbase = grp * PPC + (p & ~31);
    const int jb0 = (warpbase - 48 + h * (NP / 2) + NP) & (NP - 1);  // 16-aligned

    for (int t = 0; t < NP / 32; ++t) {        // 32 iters of 16 j
        const int jj = (jb0 + t * 16) & (NP - 1);
        const float* xbp = shx + jj;

        ull aa0=0,aa1=0,aa2=0,aa3=0,aa4=0,aa5=0,aa6=0,aa7=0;
        ull ab0=0,ab1=0,ab2=0,ab3=0,ab4=0,ab5=0,ab6=0,ab7=0;
        #pragma unroll
        for (int c = 0; c < F; ++c) {
            const ulonglong2* bp = (const ulonglong2*)(xbp + c * NP);
            ulonglong2 L0 = bp[0], L1 = bp[1], L2 = bp[2], L3 = bp[3];
            ull pa = pack2(xa[c], xa[c]);
            ull pb = pack2(xb[c], xb[c]);
            FMA2_ACC(aa0, pa, L0.x); FMA2_ACC(aa1, pa, L0.y);
            FMA2_ACC(aa2, pa, L1.x); FMA2_ACC(aa3, pa, L1.y);
            FMA2_ACC(aa4, pa, L2.x); FMA2_ACC(aa5, pa, L2.y);
            FMA2_ACC(aa6, pa, L3.x); FMA2_ACC(aa7, pa, L3.y);
            FMA2_ACC(ab0, pb, L0.x); FMA2_ACC(ab1, pb, L0.y);
            FMA2_ACC(ab2, pb, L1.x); FMA2_ACC(ab3, pb, L1.y);
            FMA2_ACC(ab4, pb, L2.x); FMA2_ACC(ab5, pb, L2.y);
            FMA2_ACC(ab6, pb, L3.x); FMA2_ACC(ab7, pb, L3.y);
        }

        float rj[16];
        #pragma unroll
        for (int q = 0; q < 4; ++q) {
            float4 rr = *(const float4*)(rsh + jj + q * 4);
            rj[q*4] = rr.x; rj[q*4+1] = rr.y; rj[q*4+2] = rr.z; rj[q*4+3] = rr.w;
        }
        const unsigned mwa = (mra[jj >> 5] >> (jj & 31)) & 0xffffu;
        const unsigned mwb = (mrb[jj >> 5] >> (jj & 31)) & 0xffffu;

        // ---- point A ----
        {
            float v[16];
            float lo, hi;
            unpack2(aa0, lo, hi); v[0]=lo;  v[1]=hi;
            unpack2(aa1, lo, hi); v[2]=lo;  v[3]=hi;
            unpack2(aa2, lo, hi); v[4]=lo;  v[5]=hi;
            unpack2(aa3, lo, hi); v[6]=lo;  v[7]=hi;
            unpack2(aa4, lo, hi); v[8]=lo;  v[9]=hi;
            unpack2(aa5, lo, hi); v[10]=lo; v[11]=hi;
            unpack2(aa6, lo, hi); v[12]=lo; v[13]=hi;
            unpack2(aa7, lo, hi); v[14]=lo; v[15]=hi;
            #pragma unroll
            for (int u = 0; u < 16; ++u) {
                float d = fmaf(2.f, v[u], -(ri1 + rj[u]));
                v[u] = ((mwa >> u) & 1u) ? -1.0f : d;   // exact -1 when masked
            }
            float bm = v[0];
            #pragma unroll
            for (int u = 1; u < 16; ++u) bm = fmaxf(bm, v[u]);
            if (bm > tva[K - 1]) {
                #pragma unroll
                for (int u = 0; u < 16; ++u) {
                    if (v[u] > tva[K - 1]) {   // strict: earliest-scanned wins ties
                        tva[K - 1] = v[u]; tia[K - 1] = jj + u;
                        #pragma unroll
                        for (int s = K - 1; s > 0; --s) {
                            if (tva[s] > tva[s - 1]) {
                                float fv = tva[s]; tva[s] = tva[s-1]; tva[s-1] = fv;
                                int   fi = tia[s]; tia[s] = tia[s-1]; tia[s-1] = fi;
                            }
                        }
                    }
                }
            }
        }
        // ---- point B ----
        {
            float v[16];
            float lo, hi;
            unpack2(ab0, lo, hi); v[0]=lo;  v[1]=hi;
            unpack2(ab1, lo, hi); v[2]=lo;  v[3]=hi;
            unpack2(ab2, lo, hi); v[4]=lo;  v[5]=hi;
            unpack2(ab3, lo, hi); v[6]=lo;  v[7]=hi;
            unpack2(ab4, lo, hi); v[8]=lo;  v[9]=hi;
            unpack2(ab5, lo, hi); v[10]=lo; v[11]=hi;
            unpack2(ab6, lo, hi); v[12]=lo; v[13]=hi;
            unpack2(ab7, lo, hi); v[14]=lo; v[15]=hi;
            #pragma unroll
            for (int u = 0; u < 16; ++u) {
                float d = fmaf(2.f, v[u], -(ri2 + rj[u]));
                v[u] = ((mwb >> u) & 1u) ? -1.0f : d;
            }
            float bm = v[0];
            #pragma unroll
            for (int u = 1; u < 16; ++u) bm = fmaxf(bm, v[u]);
            if (bm > tvb[K - 1]) {
                #pragma unroll
                for (int u = 0; u < 16; ++u) {
                    if (v[u] > tvb[K - 1]) {
                        tvb[K - 1] = v[u]; tib[K - 1] = jj + u;
                        #pragma unroll
                        for (int s = K - 1; s > 0; --s) {
                            if (tvb[s] > tvb[s - 1]) {
                                float fv = tvb[s]; tvb[s] = tvb[s-1]; tvb[s-1] = fv;
                                int   fi = tib[s]; tib[s] = tib[s-1]; tib[s-1] = fi;
                            }
                        }
                    }
                }
            }
        }
    }

    // ---- publish partials: phv[h][local_point][k] ----
    {
        float* pv = phv + h * PPC * K;
        int*   pi = phi + h * PPC * K;
        #pragma unroll
        for (int t = 0; t < K; ++t) {
            pv[p * K + t]        = tva[t];  pi[p * K + t]        = tia[t];
            pv[(p + HP) * K + t] = tvb[t];  pi[(p + HP) * K + t] = tib[t];
        }
    }
    __syncthreads();

    // ---- merge: thread tid owns point lp = tid (exact top_k comparator) ----
    int msel[K];
    {
        const float* av = phv + tid * K;            // h=0 partial
        const int*   ai_ = phi + tid * K;
        const float* bv = phv + PPC * K + tid * K;  // h=1 partial
        const int*   bi_ = phi + PPC * K + tid * K;
        int ai = 0, bi = 0;
        #pragma unroll
        for (int t = 0; t < K; ++t) {
            float avv = av[ai]; int aii = ai_[ai];
            float bvv = bv[bi]; int bii = bi_[bi];
            bool takeA = (avv > bvv) || (avv == bvv && aii < bii);
            msel[t] = takeA ? aii : bii;
            if (takeA) ++ai; else ++bi;
        }
    }

    // ---- mean of selected neighbors + epilogue (1 point per thread) ----
    const int ip = grp * PPC + tid;   // == i1 for h==0 threads, i2 for h==1
    float xiv[F];
    #pragma unroll
    for (int c = 0; c < F; ++c) xiv[c] = (h == 0) ? xa[c] : xb[c];

    float m[F];
    #pragma unroll
    for (int c = 0; c < F; ++c) m[c] = 0.f;
    #pragma unroll
    for (int t = 0; t < K; ++t) {
        int j = msel[t];
        #pragma unroll
        for (int c = 0; c < F; ++c) m[c] += shx[c * NP + j];
    }
    #pragma unroll
    for (int c = 0; c < F; ++c) m[c] *= 0.125f;

    float* ob = out + (size_t)batch * OC * NP + ip;
    #pragma unroll
    for (int o = 0; o < OC; ++o) {
        float acc = cvec[o];
        #pragma unroll
        for (int c = 0; c < F; ++c) {
            acc = fmaf(xiv[c], wsum[o * F + c], acc);
            acc = fmaf(-m[c],  wdif[o * F + c], acc);
        }
        ob[o * NP] = acc;
    }
}

extern "C" void kernel_launch(void* const* d_in, const int* in_sizes, int n_in,
                              void* d_out, int out_size)
{
    (void)in_sizes; (void)n_in; (void)out_size;
    const float* x    = (const float*)d_in[0];
    const float* mask = (const float*)d_in[1];
    const float* Wd   = (const float*)d_in[2];
    const float* bd   = (const float*)d_in[3];
    const float* Ws   = (const float*)d_in[4];
    const float* bs   = (const float*)d_in[5];
    const float* bias = (const float*)d_in[6];
    // d_in[7] = k (fixed at 8)

    cudaFuncSetAttribute(nla_kernel, cudaFuncAttributeMaxDynamicSharedMemorySize,
                         SMEM_FLOATS * (int)sizeof(float));

    nla_kernel<<<B * PG, TPB, SMEM_FLOATS * sizeof(float)>>>(
        x, mask, Wd, bd, Ws, bs, bias, (float*)d_out);
}

// round 11
// speedup vs baseline: 1.0241x; 1.0241x over previous
#include <cuda_runtime.h>
#include <cstdint>
#include <cstddef>

#define B   32
#define F   32
#define NP  1024
#define OC  32
#define K   8
#define TPB 256
#define PG  (NP / TPB)   // 4 point-groups per batch
#define MW  33           // padded words per bitmask row (conflict-free)

typedef unsigned long long ull;

// ---- f32x2 packed helpers (sm_103a full-rate fp32 path) ----
__device__ __forceinline__ ull pack2(float lo, float hi) {
    ull r; asm("mov.b64 %0, {%1, %2};" : "=l"(r) : "f"(lo), "f"(hi)); return r;
}
__device__ __forceinline__ void unpack2(ull v, float& lo, float& hi) {
    asm("mov.b64 {%0, %1}, %2;" : "=f"(lo), "=f"(hi) : "l"(v));
}
#define FMA2_ACC(d, a, b) asm("fma.rn.f32x2 %0, %1, %2, %0;" : "+l"(d) : "l"(a), "l"(b))

// smem: shx[F][NP] | rsh[NP] | wsum[OC*F] | wdif[OC*F] | cvec[OC] | mbits[TPB][MW]
#define SMEM_FLOATS (F * NP + NP + OC * F + OC * F + OC + TPB * MW)

extern "C" __global__ void __launch_bounds__(TPB, 1)
nla_kernel(const float* __restrict__ x, const float* __restrict__ mask,
           const float* __restrict__ Wd, const float* __restrict__ bd,
           const float* __restrict__ Ws, const float* __restrict__ bs,
           const float* __restrict__ bias, float* __restrict__ out)
{
    extern __shared__ float smem[];
    float*    shx   = smem;                 // [F][NP]
    float*    rsh   = smem + F * NP;        // [NP]
    float*    wsum  = rsh + NP;             // [OC*F]  (Wd + Ws)
    float*    wdif  = wsum + OC * F;        // [OC*F]
    float*    cvec  = wdif + OC * F;        // [OC]
    unsigned* mbits = (unsigned*)(cvec + OC);  // [TPB][MW] per-point bitmasks

    const int tid   = threadIdx.x;
    const int batch = blockIdx.x / PG;
    const int grp   = blockIdx.x % PG;
    const int i     = grp * TPB + tid;      // point index in [0,NP)
    (void)mask;

    // ---- stage x[batch] (feature-major, contiguous) into smem via float4 ----
    {
        const float4* xg = (const float4*)(x + (size_t)batch * F * NP);
        float4* xs = (float4*)shx;
        #pragma unroll
        for (int t = 0; t < (F * NP / 4) / TPB; ++t)
            xs[tid + t * TPB] = xg[tid + t * TPB];
    }
    // ---- stage weights ----
    for (int t = tid; t < OC * F; t += TPB) {
        float wd = Wd[t];
        wdif[t] = wd;
        wsum[t] = wd + Ws[t];
    }
    if (tid < OC) cvec[tid] = bd[tid] + bs[tid] + bias[tid];

    // ---- build per-point mask bitmap from index math (== make_local_mask(32,32)) ----
    {
        unsigned* row = mbits + tid * MW;
        #pragma unroll
        for (int w = 0; w < NP / 32; ++w) row[w] = 0u;

        int idx[8]; int n;
        const int ii = i;
        if (ii == 0)              { idx[0]=1;    idx[1]=32;   idx[2]=33;   n=3; }
        else if (ii == NP - 1)    { idx[0]=1022; idx[1]=991;  idx[2]=990;  n=3; }
        else if (ii == 31)        { idx[0]=30;   idx[1]=63;   idx[2]=62;   n=3; }
        else if (ii == NP - 32)   { idx[0]=993;  idx[1]=960;  idx[2]=961;  n=3; }
        else if (ii < 31)         { idx[0]=ii+1; idx[1]=ii-1; idx[2]=ii+31;
                                    idx[3]=ii+32; idx[4]=ii+33; n=5; }
        else if (ii > NP - 32)    { idx[0]=ii+1; idx[1]=ii-1; idx[2]=ii-33;
                                    idx[3]=ii-32; idx[4]=ii-31; n=5; }
        else if ((ii & 31) == 0)  { idx[0]=ii+1; idx[1]=ii-32; idx[2]=ii+32;
                                    idx[3]=ii-31; idx[4]=ii+33; n=5; }
        else if ((ii & 31) == 31) { idx[0]=ii-1; idx[1]=ii-32; idx[2]=ii+32;
                                    idx[3]=ii-33; idx[4]=ii+31; n=5; }
        else                      { idx[0]=ii+1; idx[1]=ii-1; idx[2]=ii-32;
                                    idx[3]=ii-31; idx[4]=ii-33; idx[5]=ii+32;
                                    idx[6]=ii+33; idx[7]=ii+31; n=8; }
        for (int t = 0; t < n; ++t)
            row[idx[t] >> 5] |= 1u << (idx[t] & 31);
    }
    __syncthreads();

    // ---- r[j] = sum_c x[c][j]^2 ----
    #pragma unroll
    for (int t = 0; t < NP / TPB; ++t) {
        int j = tid + t * TPB;
        float s = 0.f;
        #pragma unroll
        for (int c = 0; c < F; ++c) { float v = shx[c * NP + j]; s = fmaf(v, v, s); }
        rsh[j] = s;
    }
    __syncthreads();

    // ---- preload x_i as packed (v,v) pairs (64 regs) ----
    ull xi2[F];
    #pragma unroll
    for (int c = 0; c < F; ++c) { float v = shx[c * NP + i]; xi2[c] = pack2(v, v); }
    const float ri = rsh[i];

    // ---- top-8 state (value desc; strict > keeps earliest-scanned among ties,
    //      which with the window-first ascending scan == smallest index,
    //      matching lax.top_k) ----
    float tv[K]; int ti[K];
    #pragma unroll
    for (int t = 0; t < K; ++t) { tv[t] = -3.4e38f; ti[t] = 0; }

    const unsigned* mrow_bits = mbits + tid * MW;

    // Scan start: 32-aligned, just before this warp's local-mask window
    // (union over the warp: [wb-33, wb+64]); windows are visited contiguously
    // in ascending index order, so tv[7] hits the -1 tie plateau immediately.
    const int warpbase = grp * TPB + (tid & ~31);
    const int jb0 = (warpbase - 64 + NP) & (NP - 1);   // multiple of 32

    for (int t = 0; t < NP / 32; ++t) {
        const int jj = (jb0 + t * 32) & (NP - 1);
        const float* xb = shx + jj;

        // prefetch selection operands first (latency hidden under the c-loop)
        const unsigned mword = mrow_bits[jj >> 5];     // exact word: jj 32-aligned
        float rj[32];
        #pragma unroll
        for (int q = 0; q < 8; ++q) {
            float4 rr = *(const float4*)(rsh + jj + q * 4);
            rj[q*4] = rr.x; rj[q*4+1] = rr.y; rj[q*4+2] = rr.z; rj[q*4+3] = rr.w;
        }

        ull acc[16];
        #pragma unroll
        for (int q = 0; q < 16; ++q) acc[q] = 0ull;    // packed (0,0)

        #pragma unroll
        for (int c = 0; c < F; ++c) {
            const ulonglong2* bp = (const ulonglong2*)(xb + c * NP);
            #pragma unroll
            for (int q = 0; q < 8; ++q) {
                ulonglong2 L = bp[q];
                FMA2_ACC(acc[2*q],     xi2[c], L.x);
                FMA2_ACC(acc[2*q + 1], xi2[c], L.y);
            }
        }

        float v[32];
        #pragma unroll
        for (int q = 0; q < 16; ++q) {
            float lo, hi; unpack2(acc[q], lo, hi);
            float d0 = fmaf(2.f, lo, -(ri + rj[2*q]));
            float d1 = fmaf(2.f, hi, -(ri + rj[2*q + 1]));
            v[2*q]     = ((mword >> (2*q))     & 1u) ? -1.0f : d0;  // exact -1
            v[2*q + 1] = ((mword >> (2*q + 1)) & 1u) ? -1.0f : d1;
        }

        // block-max prefilter: one branch per 32 candidates
        float bm = v[0];
        #pragma unroll
        for (int u = 1; u < 32; ++u) bm = fmaxf(bm, v[u]);
        if (bm > tv[K - 1]) {
            #pragma unroll
            for (int u = 0; u < 32; ++u) {
                if (v[u] > tv[K - 1]) {        // strict: earlier-scanned wins ties
                    tv[K - 1] = v[u]; ti[K - 1] = jj + u;
                    #pragma unroll
                    for (int s = K - 1; s > 0; --s) {
                        if (tv[s] > tv[s - 1]) {
                            float fv = tv[s]; tv[s] = tv[s - 1]; tv[s - 1] = fv;
                            int   fi = ti[s]; ti[s] = ti[s - 1]; ti[s - 1] = fi;
                        }
                    }
                }
            }
        }
    }

    // ---- mean of selected neighbors (set is order-invariant) ----
    float m[F];
    #pragma unroll
    for (int c = 0; c < F; ++c) m[c] = 0.f;
    #pragma unroll
    for (int t = 0; t < K; ++t) {
        int j = ti[t];
        #pragma unroll
        for (int c = 0; c < F; ++c) m[c] += shx[c * NP + j];
    }
    const float invk = 1.f / (float)K;
    #pragma unroll
    for (int c = 0; c < F; ++c) m[c] *= invk;

    // ---- epilogue: out = xi @ (Wd+Ws)^T - m @ Wd^T + (bd+bs+bias) ----
    float xiv[F];
    #pragma unroll
    for (int c = 0; c < F; ++c) { float a, b2; unpack2(xi2[c], a, b2); xiv[c] = a; }

    float* ob = out + (size_t)batch * OC * NP + i;
    #pragma unroll
    for (int o = 0; o < OC; ++o) {
        float acc = cvec[o];
        #pragma unroll
        for (int c = 0; c < F; ++c) {
            acc = fmaf(xiv[c], wsum[o * F + c], acc);
            acc = fmaf(-m[c],  wdif[o * F + c], acc);
        }
        ob[o * NP] = acc;
    }
}

extern "C" void kernel_launch(void* const* d_in, const int* in_sizes, int n_in,
                              void* d_out, int out_size)
{
    (void)in_sizes; (void)n_in; (void)out_size;
    const float* x    = (const float*)d_in[0];
    const float* mask = (const float*)d_in[1];
    const float* Wd   = (const float*)d_in[2];
    const float* bd   = (const float*)d_in[3];
    const float* Ws   = (const float*)d_in[4];
    const float* bs   = (const float*)d_in[5];
    const float* bias = (const float*)d_in[6];
    // d_in[7] = k (fixed at 8)

    cudaFuncSetAttribute(nla_kernel, cudaFuncAttributeMaxDynamicSharedMemorySize,
                         SMEM_FLOATS * (int)sizeof(float));

    nla_kernel<<<B * PG, TPB, SMEM_FLOATS * sizeof(float)>>>(
        x, mask, Wd, bd, Ws, bs, bias, (float*)d_out);
}